// round 7
// baseline (speedup 1.0000x reference)
#include <cuda_runtime.h>
#include <math.h>

#define T_LEN    8192
#define NDELAY   360
#define NTHREADS 512
#define ELEMS    (T_LEN / NTHREADS)   // 16
#define PAD_A    848                  // >= 2*420 (pass2 reads A at lag <= 840)
#define PAD_B    1696                 // >= 4*420 (chunk reads B at lag <= 1680)
#define BUFA_LEN (T_LEN + PAD_A)
#define BUFB_LEN (T_LEN + PAD_B)
#define SKIP_TH  1e-5f

// ---------------------------------------------------------------------------
// y = x/(1+s), s = a1 z^-L1 + a2 z^-L2 (two taps: straight-through one-hot is
// exactly hard in fp32). Fixed K=2 squaring:
//   y = x (1-s)(1+s^2) / (1 - s^4)
// pass1: A = (1-s)x        -- reads x from GLOBAL (no staging pass)
// pass2: B = (1+s^2)A      -- center carried in registers
// chunks: y += s^4 y on B, width W=4*min(L1,L2); first chunk is a no-op
//         (all lags >= W) so it is a pure copy-out with no barrier; every
//         round dual-stores (STS for later taps + STG to out) so there is
//         no separate writeback pass. If rho^4 = (|a1|+|a2|)^4 < 1e-5 the
//         remainder is identity to ~1e-5 (<< 1e-3 tol) and the serial phase
//         is skipped entirely (pass2 STGs straight from registers).
// ---------------------------------------------------------------------------

__device__ __forceinline__ float tanh_fast(float x) {
    x = fminf(fmaxf(x, -15.0f), 15.0f);
    float e = __expf(2.0f * x);
    return (e - 1.0f) * __frcp_rn(e + 1.0f);
}

__global__ void __launch_bounds__(NTHREADS, 1)
ks_fused_kernel(const float* __restrict__ x,
                const float* __restrict__ gumbel,
                const float* __restrict__ delayp,
                const float* __restrict__ fb,
                const float* __restrict__ rc,
                float* __restrict__ out) {
    extern __shared__ float smem[];
    float* bufA = smem;                  // [BUFA_LEN], data at +PAD_A
    float* bufB = smem + BUFA_LEN;       // [BUFB_LEN], data at +PAD_B
    float* A = bufA + PAD_A;
    float* B = bufB + PAD_B;

    __shared__ float s_rv[16];
    __shared__ int   s_ri[16];
    __shared__ int   s_m;

    const int tid  = threadIdx.x;
    const int row  = blockIdx.x;
    const int lane = tid & 31;
    const int wid  = tid >> 5;
    const float* xr = x + (size_t)row * T_LEN;
    float*       yr = out + (size_t)row * T_LEN;

    // --- zero pads (guard-free taps later) ---
#pragma unroll
    for (int i = 0; i < 2; i++) {
        const int p = i * NTHREADS + tid;
        if (p < PAD_A) bufA[p] = 0.0f;
    }
#pragma unroll
    for (int i = 0; i < 4; i++) {
        const int p = i * NTHREADS + tid;
        if (p < PAD_B) bufB[p] = 0.0f;
    }

    // --- argmax over 360 logits (first-index tie-break) ---
    float lv = -INFINITY;
    int   li = tid;
    if (tid < NDELAY) lv = delayp[tid] + gumbel[tid];
#pragma unroll
    for (int off = 16; off > 0; off >>= 1) {
        float ov = __shfl_down_sync(0xffffffffu, lv, off);
        int   oi = __shfl_down_sync(0xffffffffu, li, off);
        if (ov > lv || (ov == lv && oi < li)) { lv = ov; li = oi; }
    }
    if (lane == 0) { s_rv[wid] = lv; s_ri[wid] = li; }

    // --- scalar coefficients (redundant per thread; fast intrinsics) ---
    float k1 = tanh_fast(tanh_fast(rc[0]));
    float k2 = tanh_fast(tanh_fast(rc[1]));
    float a1 = k1 * (1.0f - k2);
    float a2 = fminf(fmaxf(k2, -0.999f), 0.999f);
    float bound = 0.999f - fabsf(a2);
    a1 = fminf(fmaxf(a1, -bound), bound);
    float sg = __frcp_rn(1.0f + __expf(-fb[0]));
    float g  = __powf(sg, 0.45f);
    a1 *= g;
    a2 *= g;

    __syncthreads();   // s_rv/s_ri ready (also covers pad zeroing)
    if (tid < 32) {
        lv = (lane < 16) ? s_rv[lane] : -INFINITY;
        li = (lane < 16) ? s_ri[lane] : 0x7fffffff;
#pragma unroll
        for (int off = 8; off > 0; off >>= 1) {
            float ov = __shfl_down_sync(0xffffffffu, lv, off);
            int   oi = __shfl_down_sync(0xffffffffu, li, off);
            if (ov > lv || (ov == lv && oi < li)) { lv = ov; li = oi; }
        }
        if (lane == 0) s_m = li;
    }
    __syncthreads();

    const int m  = s_m;
    const int L1 = 61 + m;
    const int L2 = 61 + ((m + 1) % NDELAY);
    const int C  = (L1 < L2) ? L1 : L2;

    const float rho  = fabsf(a1) + fabsf(a2);
    const float rho2 = rho * rho;
    const bool  trunc = (rho2 * rho2) < SKIP_TH;

    // --- pass 1: A = (1 - s) x  (x read from global; guarded taps) ---
    float r[ELEMS];
#pragma unroll
    for (int i = 0; i < ELEMS; i++) {
        const int t = i * NTHREADS + tid;
        float xv = xr[t];
        float v1 = (t >= L1) ? xr[t - L1] : 0.0f;
        float v2 = (t >= L2) ? xr[t - L2] : 0.0f;
        float w = xv - a1 * v1 - a2 * v2;
        A[t] = w;
        r[i] = w;
    }
    __syncthreads();

    // --- pass 2: B = (1 + s^2) A  (center from registers) ---
    {
        const float c20 = a1 * a1;
        const float c21 = 2.0f * a1 * a2;
        const float c22 = a2 * a2;
        const int   g20 = 2 * L1;
        const int   g21 = L1 + L2;
        const int   g22 = 2 * L2;
        if (trunc) {
            // remainder ~identity: write final result straight to global
#pragma unroll
            for (int i = 0; i < ELEMS; i++) {
                const int t = i * NTHREADS + tid;
                float acc = r[i];
                acc += c20 * A[t - g20];
                acc += c21 * A[t - g21];
                acc += c22 * A[t - g22];
                yr[t] = acc;
            }
            return;
        }
#pragma unroll
        for (int i = 0; i < ELEMS; i++) {
            const int t = i * NTHREADS + tid;
            float acc = r[i];
            acc += c20 * A[t - g20];
            acc += c21 * A[t - g21];
            acc += c22 * A[t - g22];
            B[t] = acc;
        }
        __syncthreads();
    }

    // --- chunk phase on B:  y += s^4 y, width W = 4C ---
    {
        const float a1_2 = a1 * a1, a2_2 = a2 * a2;
        const float c0 = a1_2 * a1_2;
        const float c1 = 4.0f * a1_2 * a1 * a2;
        const float c2 = 6.0f * a1_2 * a2_2;
        const float c3 = 4.0f * a1 * a2_2 * a2;
        const float c4 = a2_2 * a2_2;
        const int   g0 = 4 * L1;
        const int   g1 = 3 * L1 + L2;
        const int   g2 = 2 * L1 + 2 * L2;
        const int   g3 = L1 + 3 * L2;
        const int   g4 = 4 * L2;
        const int   W  = 4 * C;

        // chunk 0 is a no-op (all lags >= W): pure copy-out, no barrier
        {
            const int end = (W < T_LEN) ? W : T_LEN;
            for (int t = tid; t < end; t += NTHREADS) yr[t] = B[t];
        }
        // serial rounds; round at s0=W reads only pass2 data + chunk 0
        // (unchanged), so no barrier before it; barrier between later rounds.
        for (int s0 = W; s0 < T_LEN; s0 += W) {
            if (s0 > W) __syncthreads();
            const int end = (s0 + W < T_LEN) ? (s0 + W) : T_LEN;
            const bool last = (s0 + W >= T_LEN);
            for (int t = s0 + tid; t < end; t += NTHREADS) {
                float acc = B[t];
                acc += c0 * B[t - g0];
                acc += c1 * B[t - g1];
                acc += c2 * B[t - g2];
                acc += c3 * B[t - g3];
                acc += c4 * B[t - g4];
                if (!last) B[t] = acc;   // nobody reads the last round
                yr[t] = acc;
            }
        }
    }
}

// ---------------------------------------------------------------------------
// inputs: excitation[128*8192] f32, gumbel[360], delay_param[360],
//         feedback_gain[1], reflection_coeffs[2]; output f32 [128*8192]
// ---------------------------------------------------------------------------
extern "C" void kernel_launch(void* const* d_in, const int* in_sizes, int n_in,
                              void* d_out, int out_size) {
    const float* x      = (const float*)d_in[0];
    const float* gumbel = (const float*)d_in[1];
    const float* delayp = (const float*)d_in[2];
    const float* fb     = (const float*)d_in[3];
    const float* rc     = (const float*)d_in[4];
    float* out = (float*)d_out;

    const int rows = in_sizes[0] / T_LEN;
    const int smem_bytes = (BUFA_LEN + BUFB_LEN) * sizeof(float);

    cudaFuncSetAttribute(ks_fused_kernel,
                         cudaFuncAttributeMaxDynamicSharedMemorySize, smem_bytes);
    ks_fused_kernel<<<rows, NTHREADS, smem_bytes>>>(x, gumbel, delayp, fb, rc, out);
}

// round 8
// speedup vs baseline: 1.4328x; 1.4328x over previous
#include <cuda_runtime.h>
#include <math.h>

#define T_LEN    8192
#define NDELAY   360
#define NTHREADS 512
#define SPAD     128
#define FULLMASK 0xffffffffu

// ---------------------------------------------------------------------------
// y_t = x_t - a1*y_{t-L1} - a2*y_{t-L2}; two taps (straight-through one-hot is
// exactly hard in fp32), L1 = 61+m, L2 = 61+((m+1)%360).
// Typical case m != 359: L2 = L1+1. With chunk width W = C = L1:
//   tap1 of round r = previous round, SAME lane slot  -> register carry
//   tap2           = previous round, one position back -> __shfl_up
// so the serial phase runs in one warp: no smem stores, no barriers, pure
// register/shuffle chain (~38 cyc/round). Other warps stage x and exit.
// Fallback (m==359 wrap, or C>128): fused R1-style barrier rounds.
// ---------------------------------------------------------------------------

__device__ __forceinline__ float tanh_fast(float x) {
    x = fminf(fmaxf(x, -15.0f), 15.0f);
    float e = __expf(2.0f * x);
    return (e - 1.0f) * __frcp_rn(e + 1.0f);
}

template <int Q>
__device__ __forceinline__ void serial_fast(const float* __restrict__ A,
                                            float* __restrict__ yr,
                                            float a1, float a2, int C) {
    const int lane = threadIdx.x & 31;
    const int lt   = (C - 1) & 31;     // lane holding last element (iter Q-1)

    float yp[Q];
    bool  act[Q];
    // round 0 = copy region [0, C): y = x
#pragma unroll
    for (int j = 0; j < Q; j++) {
        const int p = 32 * j + lane;
        act[j] = p < C;
        yp[j]  = A[p];
        if (act[j]) yr[p] = yp[j];
    }
    float tailA = __shfl_sync(FULLMASK, yp[Q - 1], lt);  // y[C-1]   (round r-1 tail)
    float tailB = 0.0f;                                  // y[-1]    (round r-2 tail)

    for (int s0 = C; s0 < T_LEN; s0 += C) {
        // prefetch centers (independent of the shuffle chain)
        float cx[Q];
#pragma unroll
        for (int j = 0; j < Q; j++) cx[j] = A[s0 + 32 * j + lane];  // pad-safe

        float yn[Q];
#pragma unroll
        for (int j = 0; j < Q; j++) {
            float t2 = __shfl_up_sync(FULLMASK, yp[j], 1);
            float b  = (j == 0) ? tailB : __shfl_sync(FULLMASK, yp[j - 1], 31);
            if (lane == 0) t2 = b;
            float acc = fmaf(-a1, yp[j], cx[j]);
            yn[j] = fmaf(-a2, t2, acc);
        }
        tailB = tailA;
        tailA = __shfl_sync(FULLMASK, yn[Q - 1], lt);
#pragma unroll
        for (int j = 0; j < Q; j++) {
            const int t = s0 + 32 * j + lane;
            if (act[j] && t < T_LEN) yr[t] = yn[j];
            yp[j] = yn[j];
        }
    }
}

__global__ void __launch_bounds__(NTHREADS, 1)
ks_fused_kernel(const float* __restrict__ x,
                const float* __restrict__ gumbel,
                const float* __restrict__ delayp,
                const float* __restrict__ fb,
                const float* __restrict__ rc,
                float* __restrict__ out) {
    extern __shared__ float A[];        // [T_LEN + SPAD]

    __shared__ float s_rv[16];
    __shared__ int   s_ri[16];
    __shared__ int   s_m;

    const int tid  = threadIdx.x;
    const int row  = blockIdx.x;
    const int lane = tid & 31;
    const int wid  = tid >> 5;
    const float* xr = x + (size_t)row * T_LEN;
    float*       yr = out + (size_t)row * T_LEN;

    // --- stage x into smem (coalesced float4), zero the tail pad ---
    {
        const float4* x4 = (const float4*)xr;
        float4* a4 = (float4*)A;
#pragma unroll
        for (int i = 0; i < T_LEN / 4 / NTHREADS; i++)
            a4[tid + i * NTHREADS] = x4[tid + i * NTHREADS];
        if (tid < SPAD) A[T_LEN + tid] = 0.0f;
    }

    // --- argmax over 360 logits (first-index tie-break) ---
    float lv = -INFINITY;
    int   li = tid;
    if (tid < NDELAY) lv = delayp[tid] + gumbel[tid];
#pragma unroll
    for (int off = 16; off > 0; off >>= 1) {
        float ov = __shfl_down_sync(FULLMASK, lv, off);
        int   oi = __shfl_down_sync(FULLMASK, li, off);
        if (ov > lv || (ov == lv && oi < li)) { lv = ov; li = oi; }
    }
    if (lane == 0) { s_rv[wid] = lv; s_ri[wid] = li; }

    // --- scalar coefficients (redundant per thread; fast intrinsics) ---
    float k1 = tanh_fast(tanh_fast(rc[0]));
    float k2 = tanh_fast(tanh_fast(rc[1]));
    float a1 = k1 * (1.0f - k2);
    float a2 = fminf(fmaxf(k2, -0.999f), 0.999f);
    float bound = 0.999f - fabsf(a2);
    a1 = fminf(fmaxf(a1, -bound), bound);
    float sg = __frcp_rn(1.0f + __expf(-fb[0]));
    float g  = __powf(sg, 0.45f);
    a1 *= g;
    a2 *= g;

    __syncthreads();
    if (tid < 32) {
        lv = (lane < 16) ? s_rv[lane] : -INFINITY;
        li = (lane < 16) ? s_ri[lane] : 0x7fffffff;
#pragma unroll
        for (int off = 8; off > 0; off >>= 1) {
            float ov = __shfl_down_sync(FULLMASK, lv, off);
            int   oi = __shfl_down_sync(FULLMASK, li, off);
            if (ov > lv || (ov == lv && oi < li)) { lv = ov; li = oi; }
        }
        if (lane == 0) s_m = li;
    }
    __syncthreads();   // staging + argmax complete

    const int m  = s_m;
    const int L1 = 61 + m;
    const int L2 = 61 + ((m + 1) % NDELAY);
    const int C  = (L1 < L2) ? L1 : L2;

    const bool fast = (L1 < L2) && (L1 <= 128);

    if (fast) {
        // single-warp register/shuffle serial phase; helpers exit
        if (wid != 0) return;
        const int Q = (C + 31) >> 5;    // 2..4
        if (Q == 2)      serial_fast<2>(A, yr, a1, a2, C);
        else if (Q == 3) serial_fast<3>(A, yr, a1, a2, C);
        else             serial_fast<4>(A, yr, a1, a2, C);
        return;
    }

    // --- fallback: barrier rounds, width C, all threads (rare path) ---
    {
        // round 0: copy [0, C)
        for (int t = tid; t < C; t += NTHREADS) yr[t] = A[t];
        for (int s0 = C; s0 < T_LEN; s0 += C) {
            __syncthreads();
            const int end = (s0 + C < T_LEN) ? (s0 + C) : T_LEN;
            for (int t = s0 + tid; t < end; t += NTHREADS) {
                float v1 = (t >= L1) ? A[t - L1] : 0.0f;
                float v2 = (t >= L2) ? A[t - L2] : 0.0f;
                float y = A[t] - a1 * v1 - a2 * v2;
                A[t] = y;
                yr[t] = y;
            }
        }
    }
}

// ---------------------------------------------------------------------------
// inputs: excitation[128*8192] f32, gumbel[360], delay_param[360],
//         feedback_gain[1], reflection_coeffs[2]; output f32 [128*8192]
// ---------------------------------------------------------------------------
extern "C" void kernel_launch(void* const* d_in, const int* in_sizes, int n_in,
                              void* d_out, int out_size) {
    const float* x      = (const float*)d_in[0];
    const float* gumbel = (const float*)d_in[1];
    const float* delayp = (const float*)d_in[2];
    const float* fb     = (const float*)d_in[3];
    const float* rc     = (const float*)d_in[4];
    float* out = (float*)d_out;

    const int rows = in_sizes[0] / T_LEN;
    const int smem_bytes = (T_LEN + SPAD) * sizeof(float);

    cudaFuncSetAttribute(ks_fused_kernel,
                         cudaFuncAttributeMaxDynamicSharedMemorySize, smem_bytes);
    ks_fused_kernel<<<rows, NTHREADS, smem_bytes>>>(x, gumbel, delayp, fb, rc, out);
}